// round 15
// baseline (speedup 1.0000x reference)
#include <cuda_runtime.h>
#include <cstdint>
#include <cstddef>

#define B_ 16384
#define T_ 64
#define H_ 64
#define R_ 300

typedef unsigned long long u64;

// ---------------- packed f32x2 helpers ----------------
__device__ __forceinline__ u64 f2pk(float a, float b) {
    u64 r; asm("mov.b64 %0, {%1, %2};" : "=l"(r) : "f"(a), "f"(b)); return r;
}
__device__ __forceinline__ void f2un(u64 v, float& a, float& b) {
    asm("mov.b64 {%0, %1}, %2;" : "=f"(a), "=f"(b) : "l"(v));
}
__device__ __forceinline__ u64 ffma2(u64 a, u64 b, u64 c) {
    u64 d; asm("fma.rn.f32x2 %0, %1, %2, %3;" : "=l"(d) : "l"(a), "l"(b), "l"(c)); return d;
}
__device__ __forceinline__ float hadd2(u64 v) { float a, b; f2un(v, a, b); return a + b; }
__device__ __forceinline__ float frcp(float x) {
    float r; asm("rcp.approx.f32 %0, %1;" : "=f"(r) : "f"(x)); return r;
}
__device__ __forceinline__ float tanha_(float x) {
    float y; asm("tanh.approx.f32 %0, %1;" : "=f"(y) : "f"(x)); return y;
}
__device__ __forceinline__ float sigmoida_(float x) {
    return fmaf(0.5f, tanha_(0.5f * x), 0.5f);
}
__device__ __forceinline__ float sigmoidf_(float x) { return frcp(1.f + __expf(-x)); }
__device__ __forceinline__ float eluf_(float x) {
    float e = __expf(x) - 1.f;
    return x > 0.f ? x : e;
}

// ---------------- device scratch ----------------
__device__ float g_hidT[B_ * H_];
__device__ float g_hidM[B_ * H_];
__device__ float g_rawT[B_];
__device__ float g_rawM[B_];

// ---------------- diagnostic no-op (ncu slot -> k_mlp) -----------------
__global__ void k_nop1() {}

// ======================================================================
// Kernel 1 (v6, unchanged — 802-804us measured plateau).
// ======================================================================
#define S_STRIDE  140
#define S2_STRIDE 76
#define GRU_SMEM_FLOATS (8192 + 4096 + 64 * S_STRIDE + 64 * S2_STRIDE + 64 + 64 + 192 + 192 + 192 + 128 + 128 + 128)
#define GRU_SMEM_BYTES  (GRU_SMEM_FLOATS * 4)

__global__ void __launch_bounds__(256, 2) k_gru(
    const float* __restrict__ X_fa, const float* __restrict__ X_last,
    const float* __restrict__ X_mean, const float* __restrict__ X_mask,
    const float* __restrict__ X_delta,
    const float* __restrict__ W_gx, const float* __restrict__ b_gx,
    const float* __restrict__ W_gh, const float* __restrict__ b_gh,
    const float* __restrict__ W_xc, const float* __restrict__ b_xc,
    const float* __restrict__ W_hn, const float* __restrict__ W_hc,
    const float* __restrict__ W_mc,
    float* __restrict__ o_out, float* __restrict__ o_Xgru)
{
    extern __shared__ float sm[];
    float* sWzr = sm;
    float* sWn  = sm + 8192;
    float* S1   = sm + 12288;
    float* S2   = S1 + 64 * S_STRIDE;
    float* sWgh = S2 + 64 * S2_STRIDE;
    float* sBgh = sWgh + 64;
    float* sWxc = sBgh + 64;
    float* sBxc = sWxc + 192;
    float* sWmc = sBxc + 192;
    float* sXb  = sWmc + 192;
    float* sMb  = sXb + 128;
    float* sDb  = sMb + 128;

    const int tid = threadIdx.x;
    for (int i = tid; i < 8192; i += 256) sWzr[(i & 63) * 128 + (i >> 6)] = W_hc[i];
    for (int i = tid; i < 4096; i += 256) sWn[(i & 63) * 64 + (i >> 6)] = W_hn[i];
    if (tid < 64) { sWgh[tid] = W_gh[tid]; sBgh[tid] = b_gh[tid]; }
    if (tid < 192) { sWxc[tid] = W_xc[tid]; sBxc[tid] = b_xc[tid]; sWmc[tid] = W_mc[tid]; }

    const int w = tid >> 5, l = tid & 31;
    const int jt = (l & 7) | ((w & 1) << 3);
    const int rt = (l >> 3) | ((w >> 1) << 2);
    const int j0 = jt * 4, r0 = rt * 4;
    const int soff = 4 * (rt & 3);
    const int rowbase = blockIdx.x * 64;
    const float wgx = W_gx[0], bgx0 = b_gx[0];

    float h[4][4];
#pragma unroll
    for (int a = 0; a < 4; a++)
#pragma unroll
        for (int b = 0; b < 4; b++) h[a][b] = 0.f;

    const int myrow = rowbase + (tid & 63);
    float pf_xi = 0.f, pf_xl = 0.f, pf_xm = 0.f, pf_m = 0.f, pf_d = 0.f;
    if (tid < 64) {
        float xi = X_fa[(size_t)myrow * T_], xl = X_last[(size_t)myrow * T_];
        float xm = X_mean[(size_t)myrow * T_], m = X_mask[(size_t)myrow * T_];
        float d = X_delta[(size_t)myrow * T_];
        float gx = __expf(-fmaxf(fmaf(d, wgx, bgx0), 0.f));
        float om = 1.f - m;
        float Xv = m * xi + om * gx * xl + om * (1.f - gx) * xm;
        sXb[tid] = Xv; sMb[tid] = m; sDb[tid] = d;
        o_Xgru[(size_t)myrow * T_] = Xv;
        if (T_ > 1) {
            pf_xi = X_fa   [(size_t)myrow * T_ + 1];
            pf_xl = X_last [(size_t)myrow * T_ + 1];
            pf_xm = X_mean [(size_t)myrow * T_ + 1];
            pf_m  = X_mask [(size_t)myrow * T_ + 1];
            pf_d  = X_delta[(size_t)myrow * T_ + 1];
        }
    }
    __syncthreads();

    for (int t = 0; t < T_; t++) {
        const int cur = t & 1;

#pragma unroll
        for (int rr = 0; rr < 4; rr++) {
            const float d = sDb[cur * 64 + r0 + rr];
#pragma unroll
            for (int jj = 0; jj < 4; jj++) {
                float g = __expf(-fmaxf(fmaf(d, sWgh[j0 + jj], sBgh[j0 + jj]), 0.f));
                h[rr][jj] *= g;
            }
            float* base = S1 + (r0 + rr) * S_STRIDE + soff + 2 * j0;
            float4 a; a.x = h[rr][0]; a.y = h[rr][0]; a.z = h[rr][1]; a.w = h[rr][1];
            float4 b; b.x = h[rr][2]; b.y = h[rr][2]; b.z = h[rr][3]; b.w = h[rr][3];
            *(float4*)(base)     = a;
            *(float4*)(base + 4) = b;
        }
        __syncthreads();

        if (tid < 64 && t + 1 < T_) {
            const float d = pf_d, m = pf_m;
            const float gx = __expf(-fmaxf(fmaf(d, wgx, bgx0), 0.f));
            const float om = 1.f - m;
            const float Xv = m * pf_xi + om * gx * pf_xl + om * (1.f - gx) * pf_xm;
            const int nc = 1 - cur;
            sXb[nc * 64 + tid] = Xv; sMb[nc * 64 + tid] = m; sDb[nc * 64 + tid] = d;
            o_Xgru[(size_t)myrow * T_ + t + 1] = Xv;
            if (t + 2 < T_) {
                pf_xi = X_fa   [(size_t)myrow * T_ + t + 2];
                pf_xl = X_last [(size_t)myrow * T_ + t + 2];
                pf_xm = X_mean [(size_t)myrow * T_ + t + 2];
                pf_m  = X_mask [(size_t)myrow * T_ + t + 2];
                pf_d  = X_delta[(size_t)myrow * T_ + t + 2];
            }
        }

        const float* sbase1 = S1 + r0 * S_STRIDE + soff;
        u64 az[4][2] = {}, ar[4][2] = {};
#pragma unroll 4
        for (int k2 = 0; k2 < 32; k2++) {
            const float* sp = sbase1 + 4 * k2;
            const ulonglong2 H0 = *(const ulonglong2*)(sp);
            const ulonglong2 H1 = *(const ulonglong2*)(sp + S_STRIDE);
            const ulonglong2 H2 = *(const ulonglong2*)(sp + 2 * S_STRIDE);
            const ulonglong2 H3 = *(const ulonglong2*)(sp + 3 * S_STRIDE);
            {
                const ulonglong2 wz = *(const ulonglong2*)(sWzr + (2 * k2) * 128 + j0);
                const ulonglong2 wr = *(const ulonglong2*)(sWzr + (2 * k2) * 128 + 64 + j0);
                az[0][0] = ffma2(H0.x, wz.x, az[0][0]); az[0][1] = ffma2(H0.x, wz.y, az[0][1]);
                az[1][0] = ffma2(H1.x, wz.x, az[1][0]); az[1][1] = ffma2(H1.x, wz.y, az[1][1]);
                az[2][0] = ffma2(H2.x, wz.x, az[2][0]); az[2][1] = ffma2(H2.x, wz.y, az[2][1]);
                az[3][0] = ffma2(H3.x, wz.x, az[3][0]); az[3][1] = ffma2(H3.x, wz.y, az[3][1]);
                ar[0][0] = ffma2(H0.x, wr.x, ar[0][0]); ar[0][1] = ffma2(H0.x, wr.y, ar[0][1]);
                ar[1][0] = ffma2(H1.x, wr.x, ar[1][0]); ar[1][1] = ffma2(H1.x, wr.y, ar[1][1]);
                ar[2][0] = ffma2(H2.x, wr.x, ar[2][0]); ar[2][1] = ffma2(H2.x, wr.y, ar[2][1]);
                ar[3][0] = ffma2(H3.x, wr.x, ar[3][0]); ar[3][1] = ffma2(H3.x, wr.y, ar[3][1]);
            }
            {
                const ulonglong2 wz = *(const ulonglong2*)(sWzr + (2 * k2 + 1) * 128 + j0);
                const ulonglong2 wr = *(const ulonglong2*)(sWzr + (2 * k2 + 1) * 128 + 64 + j0);
                az[0][0] = ffma2(H0.y, wz.x, az[0][0]); az[0][1] = ffma2(H0.y, wz.y, az[0][1]);
                az[1][0] = ffma2(H1.y, wz.x, az[1][0]); az[1][1] = ffma2(H1.y, wz.y, az[1][1]);
                az[2][0] = ffma2(H2.y, wz.x, az[2][0]); az[2][1] = ffma2(H2.y, wz.y, az[2][1]);
                az[3][0] = ffma2(H3.y, wz.x, az[3][0]); az[3][1] = ffma2(H3.y, wz.y, az[3][1]);
                ar[0][0] = ffma2(H0.y, wr.x, ar[0][0]); ar[0][1] = ffma2(H0.y, wr.y, ar[0][1]);
                ar[1][0] = ffma2(H1.y, wr.x, ar[1][0]); ar[1][1] = ffma2(H1.y, wr.y, ar[1][1]);
                ar[2][0] = ffma2(H2.y, wr.x, ar[2][0]); ar[2][1] = ffma2(H2.y, wr.y, ar[2][1]);
                ar[3][0] = ffma2(H3.y, wr.x, ar[3][0]); ar[3][1] = ffma2(H3.y, wr.y, ar[3][1]);
            }
        }

        float zreg[4][4];
#pragma unroll
        for (int rr = 0; rr < 4; rr++) {
            const int r = r0 + rr;
            const float Xv = sXb[cur * 64 + r], mv = sMb[cur * 64 + r];
            float a0, a1, a2, a3, c0, c1, c2, c3;
            f2un(az[rr][0], a0, a1); f2un(az[rr][1], a2, a3);
            f2un(ar[rr][0], c0, c1); f2un(ar[rr][1], c2, c3);
            zreg[rr][0] = sigmoida_(a0 + fmaf(Xv, sWxc[j0 + 0], sBxc[j0 + 0]) + mv * sWmc[j0 + 0]);
            zreg[rr][1] = sigmoida_(a1 + fmaf(Xv, sWxc[j0 + 1], sBxc[j0 + 1]) + mv * sWmc[j0 + 1]);
            zreg[rr][2] = sigmoida_(a2 + fmaf(Xv, sWxc[j0 + 2], sBxc[j0 + 2]) + mv * sWmc[j0 + 2]);
            zreg[rr][3] = sigmoida_(a3 + fmaf(Xv, sWxc[j0 + 3], sBxc[j0 + 3]) + mv * sWmc[j0 + 3]);
            float r0g = sigmoida_(c0 + fmaf(Xv, sWxc[64 + j0 + 0], sBxc[64 + j0 + 0]) + mv * sWmc[64 + j0 + 0]);
            float r1g = sigmoida_(c1 + fmaf(Xv, sWxc[64 + j0 + 1], sBxc[64 + j0 + 1]) + mv * sWmc[64 + j0 + 1]);
            float r2g = sigmoida_(c2 + fmaf(Xv, sWxc[64 + j0 + 2], sBxc[64 + j0 + 2]) + mv * sWmc[64 + j0 + 2]);
            float r3g = sigmoida_(c3 + fmaf(Xv, sWxc[64 + j0 + 3], sBxc[64 + j0 + 3]) + mv * sWmc[64 + j0 + 3]);
            float4 rv;
            rv.x = r0g * h[rr][0]; rv.y = r1g * h[rr][1];
            rv.z = r2g * h[rr][2]; rv.w = r3g * h[rr][3];
            *(float4*)(S2 + (r0 + rr) * S2_STRIDE + soff + j0) = rv;
        }
        __syncthreads();

        const float* sbase2 = S2 + r0 * S2_STRIDE + soff;
        u64 an[4][2] = {};
#pragma unroll 4
        for (int k4 = 0; k4 < 16; k4++) {
            const float* sp = sbase2 + 4 * k4;
            const float4 f0 = *(const float4*)(sp);
            const float4 f1 = *(const float4*)(sp + S2_STRIDE);
            const float4 f2v = *(const float4*)(sp + 2 * S2_STRIDE);
            const float4 f3 = *(const float4*)(sp + 3 * S2_STRIDE);
            const float e0[4] = {f0.x, f0.y, f0.z, f0.w};
            const float e1[4] = {f1.x, f1.y, f1.z, f1.w};
            const float e2[4] = {f2v.x, f2v.y, f2v.z, f2v.w};
            const float e3[4] = {f3.x, f3.y, f3.z, f3.w};
#pragma unroll
            for (int kk = 0; kk < 4; kk++) {
                const ulonglong2 wn = *(const ulonglong2*)(sWn + (4 * k4 + kk) * 64 + j0);
                u64 h0 = f2pk(e0[kk], e0[kk]);
                u64 h1 = f2pk(e1[kk], e1[kk]);
                u64 h2 = f2pk(e2[kk], e2[kk]);
                u64 h3 = f2pk(e3[kk], e3[kk]);
                an[0][0] = ffma2(h0, wn.x, an[0][0]); an[0][1] = ffma2(h0, wn.y, an[0][1]);
                an[1][0] = ffma2(h1, wn.x, an[1][0]); an[1][1] = ffma2(h1, wn.y, an[1][1]);
                an[2][0] = ffma2(h2, wn.x, an[2][0]); an[2][1] = ffma2(h2, wn.y, an[2][1]);
                an[3][0] = ffma2(h3, wn.x, an[3][0]); an[3][1] = ffma2(h3, wn.y, an[3][1]);
            }
        }

#pragma unroll
        for (int rr = 0; rr < 4; rr++) {
            const int r = r0 + rr;
            const float Xv = sXb[cur * 64 + r], mv = sMb[cur * 64 + r];
            float n0, n1, n2, n3;
            f2un(an[rr][0], n0, n1); f2un(an[rr][1], n2, n3);
            float p0 = n0 + fmaf(Xv, sWxc[128 + j0 + 0], sBxc[128 + j0 + 0]) + mv * sWmc[128 + j0 + 0];
            float p1 = n1 + fmaf(Xv, sWxc[128 + j0 + 1], sBxc[128 + j0 + 1]) + mv * sWmc[128 + j0 + 1];
            float p2 = n2 + fmaf(Xv, sWxc[128 + j0 + 2], sBxc[128 + j0 + 2]) + mv * sWmc[128 + j0 + 2];
            float p3 = n3 + fmaf(Xv, sWxc[128 + j0 + 3], sBxc[128 + j0 + 3]) + mv * sWmc[128 + j0 + 3];
            float t0 = tanha_(p0), t1 = tanha_(p1), t2 = tanha_(p2), t3 = tanha_(p3);
            h[rr][0] = fmaf(zreg[rr][0], t0 - h[rr][0], h[rr][0]);
            h[rr][1] = fmaf(zreg[rr][1], t1 - h[rr][1], h[rr][1]);
            h[rr][2] = fmaf(zreg[rr][2], t2 - h[rr][2], h[rr][2]);
            h[rr][3] = fmaf(zreg[rr][3], t3 - h[rr][3], h[rr][3]);
            float4 st; st.x = h[rr][0]; st.y = h[rr][1]; st.z = h[rr][2]; st.w = h[rr][3];
            *(float4*)(o_out + (((size_t)(rowbase + r)) * T_ + t) * H_ + j0) = st;
        }
    }
}

// ======================================================================
// Kernel 2: coalesced tile -> shared; logits + softmax + pooling.
// ======================================================================
#define ATT_S 68

__global__ void __launch_bounds__(64) k_attn(
    const float* __restrict__ out,
    const float* __restrict__ W_sT, const float* __restrict__ W_sM)
{
    __shared__ float sT[64 * ATT_S];
    __shared__ float sWt[64], sWm[64], slT[64], slM[64], swT[64], swM[64];
    const int b = blockIdx.x;
    const int tid = threadIdx.x;
    sWt[tid] = W_sT[tid]; sWm[tid] = W_sM[tid];

    const float4* src = (const float4*)(out + (size_t)b * 4096);
#pragma unroll
    for (int i = 0; i < 16; i++) {
        float4 v = src[i * 64 + tid];
        int t = 4 * i + (tid >> 4);
        int hh = (4 * tid) & 63;
        *(float4*)(sT + t * ATT_S + hh) = v;
    }
    __syncthreads();

    float lT = 0.f, lM = 0.f;
    const float* row = sT + tid * ATT_S;
#pragma unroll
    for (int i = 0; i < 16; i++) {
        float4 v = *(const float4*)(row + 4 * i);
        lT += v.x * sWt[4 * i] + v.y * sWt[4 * i + 1] + v.z * sWt[4 * i + 2] + v.w * sWt[4 * i + 3];
        lM += v.x * sWm[4 * i] + v.y * sWm[4 * i + 1] + v.z * sWm[4 * i + 2] + v.w * sWm[4 * i + 3];
    }
    slT[tid] = lT; slM[tid] = lM;
    __syncthreads();

    const int wid = tid >> 5, lane = tid & 31;
    const float* lg = wid ? slM : slT;
    float l0 = lg[lane], l1 = lg[lane + 32];
    float mx = fmaxf(l0, l1);
#pragma unroll
    for (int o = 16; o; o >>= 1) mx = fmaxf(mx, __shfl_xor_sync(0xffffffffu, mx, o));
    float e0 = __expf(l0 - mx), e1 = __expf(l1 - mx);
    float s = e0 + e1;
#pragma unroll
    for (int o = 16; o; o >>= 1) s += __shfl_xor_sync(0xffffffffu, s, o);
    float inv = frcp(s);
    float* sw = wid ? swM : swT;
    sw[lane] = e0 * inv; sw[lane + 32] = e1 * inv;
    __syncthreads();

    float aT = 0.f, aM = 0.f;
#pragma unroll 8
    for (int t = 0; t < 64; t++) {
        float v = sT[t * ATT_S + tid];
        aT = fmaf(swT[t], v, aT);
        aM = fmaf(swM[t], v, aM);
    }
    g_hidT[(size_t)b * 64 + tid] = aT;
    g_hidM[(size_t)b * 64 + tid] = aM;
}

// ======================================================================
// Kernel 3 (v5): MLPs, 512 threads, quarter-split rows (4 threads/row).
// Layer1: 5 stages of 60-row W1 tiles (15 outputs per quarter).
// Layer2: 15 stages of 20-row W2 tiles (5 outputs per quarter).
// Same smem as R9 but 16 warps/SM for latency hiding.
// ======================================================================
#define MLP_PAD   302
#define W1T_F4    960           /* 60 rows x 64 f32 */
#define W2T_F4    1500          /* 20 rows x 300 f32 */
#define WBUF_FL   6000
#define MLP_SMEM  ((128 * MLP_PAD + 2 * WBUF_FL + 512) * 4)

__global__ void __launch_bounds__(512) k_mlp(
    const float* __restrict__ Wt1, const float* __restrict__ bt1,
    const float* __restrict__ Wt2, const float* __restrict__ bt2,
    const float* __restrict__ Wt3, const float* __restrict__ bt3,
    const float* __restrict__ Wm1, const float* __restrict__ bm1,
    const float* __restrict__ Wm2, const float* __restrict__ bm2,
    const float* __restrict__ Wm3, const float* __restrict__ bm3)
{
    extern __shared__ float sact[];
    float* wbuf0 = sact + 128 * MLP_PAD;
    float* wbuf1 = wbuf0 + WBUF_FL;
    float* sraw  = wbuf1 + WBUF_FL;      // 512 floats

    const int head = blockIdx.y;
    const float* hid = head ? g_hidM : g_hidT;
    const float* W1 = head ? Wm1 : Wt1;  const float* b1 = head ? bm1 : bt1;
    const float* W2 = head ? Wm2 : Wt2;  const float* b2 = head ? bm2 : bt2;
    const float* W3 = head ? Wm3 : Wt3;  const float* b3 = head ? bm3 : bt3;
    float* rawOut = head ? g_rawM : g_rawT;

    const int tid  = threadIdx.x;
    const int rloc = tid & 127;          // batch row within block
    const int q    = tid >> 7;           // quarter 0..3
    const int row  = blockIdx.x * 128 + rloc;

    // ---- load hid row into regs (all 4 quarters load the same row) ----
    u64 h2[32];
    {
        const ulonglong2* hp = (const ulonglong2*)(hid + (size_t)row * 64);
#pragma unroll
        for (int i = 0; i < 16; i++) { ulonglong2 v = hp[i]; h2[2 * i] = v.x; h2[2 * i + 1] = v.y; }
    }
    float* arow = sact + rloc * MLP_PAD;

    // ============ layer 1: 64 -> 300, 5 stages of 60 rows ==============
    {
        const float4* src = (const float4*)W1;
        float4* dst = (float4*)wbuf0;
        for (int i = tid; i < W1T_F4; i += 512) dst[i] = src[i];
    }
    __syncthreads();

    int p = 0;
    for (int s = 0; s < 5; s++) {
        float4 tr[2]; int trn = 0;
        if (s + 1 < 5) {
            const float4* src = (const float4*)(W1 + (s + 1) * 3840);
#pragma unroll
            for (int i = 0; i < 2; i++) {
                int idx = tid + i * 512;
                if (idx < W1T_F4) { tr[i] = src[idx]; trn = i + 1; }
            }
        }
        const float* wt = p ? wbuf1 : wbuf0;
        for (int jj = 0; jj < 15; jj++) {
            const int jl = q * 15 + jj;
            const int j  = 60 * s + jl;
            const ulonglong2* wp = (const ulonglong2*)(wt + jl * 64);
            u64 aA = 0, aB = 0;
#pragma unroll
            for (int kk = 0; kk < 16; kk++) {
                ulonglong2 wv = wp[kk];
                aA = ffma2(h2[2 * kk], wv.x, aA);
                aB = ffma2(h2[2 * kk + 1], wv.y, aB);
            }
            arow[j] = eluf_(hadd2(aA) + hadd2(aB) + b1[j]);
        }
        if (s + 1 < 5) {
            float4* dst = (float4*)(p ? wbuf0 : wbuf1);
#pragma unroll
            for (int i = 0; i < 2; i++) {
                int idx = tid + i * 512;
                if (idx < W1T_F4 && i < trn) dst[idx] = tr[i];
            }
        }
        __syncthreads();
        p ^= 1;
    }

    // ============ layer 2+3: 15 stages of 20 rows ======================
    {
        const float4* src = (const float4*)W2;
        float4* dst = (float4*)wbuf0;
        for (int i = tid; i < W2T_F4; i += 512) dst[i] = src[i];
    }
    __syncthreads();

    float raw = 0.f;
    const u64* ap = (const u64*)arow;
    p = 0;
    for (int s = 0; s < 15; s++) {
        float4 tr[3]; int trn = 0;
        if (s + 1 < 15) {
            const float4* src = (const float4*)(W2 + (size_t)(s + 1) * 6000);
#pragma unroll
            for (int i = 0; i < 3; i++) {
                int idx = tid + i * 512;
                if (idx < W2T_F4) { tr[i] = src[idx]; trn = i + 1; }
            }
        }
        const float* wt = p ? wbuf1 : wbuf0;
        u64 aA[5], aB[5];
#pragma unroll
        for (int u = 0; u < 5; u++) { aA[u] = 0; aB[u] = 0; }
        const float* wbase = wt + (q * 5) * 300;
        for (int kk = 0; kk < 75; kk++) {
            u64 a0 = ap[2 * kk], a1 = ap[2 * kk + 1];
#pragma unroll
            for (int u = 0; u < 5; u++) {
                ulonglong2 wv = *(const ulonglong2*)(wbase + u * 300 + 4 * kk);
                aA[u] = ffma2(a0, wv.x, aA[u]);
                aB[u] = ffma2(a1, wv.y, aB[u]);
            }
        }
#pragma unroll
        for (int u = 0; u < 5; u++) {
            const int j = 20 * s + q * 5 + u;
            float sv = hadd2(aA[u]) + hadd2(aB[u]) + b2[j];
            raw = fmaf(eluf_(sv), W3[j], raw);
        }
        if (s + 1 < 15) {
            float4* dst = (float4*)(p ? wbuf0 : wbuf1);
#pragma unroll
            for (int i = 0; i < 3; i++) {
                int idx = tid + i * 512;
                if (idx < W2T_F4 && i < trn) dst[idx] = tr[i];
            }
        }
        __syncthreads();
        p ^= 1;
    }

    // ---- reduce 4 quarter-partials per row ----
    sraw[rloc * 4 + q] = raw;
    __syncthreads();
    if (tid < 128) {
        const float* sp = sraw + tid * 4;
        rawOut[blockIdx.x * 128 + tid] = sp[0] + sp[1] + sp[2] + sp[3] + b3[0];
    }
}

// ======================================================================
// Kernel 4: elementwise, fully coalesced.
// ======================================================================
__global__ void __launch_bounds__(256) k_final(
    const float* __restrict__ fa, const float* __restrict__ TR,
    float* __restrict__ o_Xout, float* __restrict__ o_T10, float* __restrict__ o_M0)
{
    const int gid = blockIdx.x * 256 + threadIdx.x;
    const int b = gid >> 6;
    const int t = gid & 63;
    const float T10 = 0.2f + sigmoidf_(g_rawT[b]) * 4.8f;
    const float M0v = 0.1f + sigmoidf_(g_rawM[b]) * 19.9f;
    if (t == 0) { o_T10[b] = T10; o_M0[b] = M0v; }
    const float e = __expf(-TR[b] / T10);
    const float f = fa[gid];
    const float num = (1.f - e) * __sinf(f);
    const float den = 1.f - __cosf(f) * e;
    o_Xout[gid] = num / den * M0v;
}

// ======================================================================
extern "C" void kernel_launch(void* const* d_in, const int* in_sizes, int n_in,
                              void* d_out, int out_size)
{
    const float* X_fa    = (const float*)d_in[0];
    const float* X_last  = (const float*)d_in[1];
    const float* X_mean  = (const float*)d_in[2];
    const float* X_mask  = (const float*)d_in[3];
    const float* X_delta = (const float*)d_in[4];
    const float* fa_vals = (const float*)d_in[5];
    const float* TR_vals = (const float*)d_in[6];
    const float* W_gx = (const float*)d_in[7];
    const float* b_gx = (const float*)d_in[8];
    const float* W_gh = (const float*)d_in[9];
    const float* b_gh = (const float*)d_in[10];
    const float* W_xc = (const float*)d_in[11];
    const float* b_xc = (const float*)d_in[12];
    const float* W_hn = (const float*)d_in[13];
    const float* W_hc = (const float*)d_in[14];
    const float* W_mc = (const float*)d_in[15];
    const float* W_sT = (const float*)d_in[16];
    const float* W_sM = (const float*)d_in[17];
    const float* Wt1 = (const float*)d_in[18];
    const float* bt1 = (const float*)d_in[19];
    const float* Wt2 = (const float*)d_in[20];
    const float* bt2 = (const float*)d_in[21];
    const float* Wt3 = (const float*)d_in[22];
    const float* bt3 = (const float*)d_in[23];
    const float* Wm1 = (const float*)d_in[24];
    const float* bm1 = (const float*)d_in[25];
    const float* Wm2 = (const float*)d_in[26];
    const float* bm2 = (const float*)d_in[27];
    const float* Wm3 = (const float*)d_in[28];
    const float* bm3 = (const float*)d_in[29];

    float* outp = (float*)d_out;
    float* o_Xout = outp;                       // [B,T]
    float* o_T10  = outp + 1048576;             // [B,1]
    float* o_M0   = outp + 1064960;             // [B,1]
    float* o_out  = outp + 1081344;             // [B,T,H]
    float* o_Xgru = outp + 68190208;            // [B,T]

    cudaFuncSetAttribute(k_gru, cudaFuncAttributeMaxDynamicSharedMemorySize, GRU_SMEM_BYTES);
    cudaFuncSetAttribute(k_mlp, cudaFuncAttributeMaxDynamicSharedMemorySize, MLP_SMEM);

    // shim: ncu capture slot -> new k_mlp
    k_nop1<<<1, 32>>>();

    k_gru<<<B_ / 64, 256, GRU_SMEM_BYTES>>>(
        X_fa, X_last, X_mean, X_mask, X_delta,
        W_gx, b_gx, W_gh, b_gh, W_xc, b_xc, W_hn, W_hc, W_mc,
        o_out, o_Xgru);

    k_attn<<<B_, 64>>>(o_out, W_sT, W_sM);

    dim3 mgrid(B_ / 128, 2);
    k_mlp<<<mgrid, 512, MLP_SMEM>>>(Wt1, bt1, Wt2, bt2, Wt3, bt3,
                                    Wm1, bm1, Wm2, bm2, Wm3, bm3);

    k_final<<<(B_ * T_) / 256, 256>>>(fa_vals, TR_vals, o_Xout, o_T10, o_M0);
}

// round 17
// speedup vs baseline: 1.1072x; 1.1072x over previous
#include <cuda_runtime.h>
#include <cstdint>
#include <cstddef>

#define B_ 16384
#define T_ 64
#define H_ 64
#define R_ 300

typedef unsigned long long u64;

// ---------------- packed f32x2 helpers ----------------
__device__ __forceinline__ u64 f2pk(float a, float b) {
    u64 r; asm("mov.b64 %0, {%1, %2};" : "=l"(r) : "f"(a), "f"(b)); return r;
}
__device__ __forceinline__ void f2un(u64 v, float& a, float& b) {
    asm("mov.b64 {%0, %1}, %2;" : "=f"(a), "=f"(b) : "l"(v));
}
__device__ __forceinline__ u64 ffma2(u64 a, u64 b, u64 c) {
    u64 d; asm("fma.rn.f32x2 %0, %1, %2, %3;" : "=l"(d) : "l"(a), "l"(b), "l"(c)); return d;
}
__device__ __forceinline__ float hadd2(u64 v) { float a, b; f2un(v, a, b); return a + b; }
__device__ __forceinline__ float frcp(float x) {
    float r; asm("rcp.approx.f32 %0, %1;" : "=f"(r) : "f"(x)); return r;
}
__device__ __forceinline__ float tanha_(float x) {
    float y; asm("tanh.approx.f32 %0, %1;" : "=f"(y) : "f"(x)); return y;
}
__device__ __forceinline__ float sigmoida_(float x) {
    return fmaf(0.5f, tanha_(0.5f * x), 0.5f);
}
__device__ __forceinline__ float sigmoidf_(float x) { return frcp(1.f + __expf(-x)); }
__device__ __forceinline__ float eluf_(float x) {
    float e = __expf(x) - 1.f;
    return x > 0.f ? x : e;
}

// ---------------- device scratch ----------------
__device__ float g_hidT[B_ * H_];
__device__ float g_hidM[B_ * H_];
__device__ float g_rawT[B_];
__device__ float g_rawM[B_];

// ---------------- diagnostic no-ops (ncu slot -> k_gru) ----------------
__global__ void k_nop1() {}
__global__ void k_nop2() {}
__global__ void k_nop3() {}

// ======================================================================
// Kernel 1 (v7b): GRU-D scan, scalar S1/S2, LDS.128-per-4k operands.
// FIX vs v7: strides 76 (=64 data + 12 max swizzle), restoring the
// overflow-free invariant from v6. Warp = 8 jt x 4 rt, soff = 4*(rt&3).
// 256 threads, 64 rows/block, 2 blocks/SM, 2 barriers/step.
// ======================================================================
#define S_STRIDE  76
#define S2_STRIDE 76
#define GRU_SMEM_FLOATS (8192 + 4096 + 64 * S_STRIDE + 64 * S2_STRIDE + 64 + 64 + 192 + 192 + 192 + 128 + 128 + 128)
#define GRU_SMEM_BYTES  (GRU_SMEM_FLOATS * 4)

__global__ void __launch_bounds__(256, 2) k_gru(
    const float* __restrict__ X_fa, const float* __restrict__ X_last,
    const float* __restrict__ X_mean, const float* __restrict__ X_mask,
    const float* __restrict__ X_delta,
    const float* __restrict__ W_gx, const float* __restrict__ b_gx,
    const float* __restrict__ W_gh, const float* __restrict__ b_gh,
    const float* __restrict__ W_xc, const float* __restrict__ b_xc,
    const float* __restrict__ W_hn, const float* __restrict__ W_hc,
    const float* __restrict__ W_mc,
    float* __restrict__ o_out, float* __restrict__ o_Xgru)
{
    extern __shared__ float sm[];
    float* sWzr = sm;                          // [64][128] W_hc^T (z | r)
    float* sWn  = sm + 8192;                   // [64][64]  W_hn^T
    float* S1   = sm + 12288;                  // [64][76] scalar h (swizzled)
    float* S2   = S1 + 64 * S_STRIDE;          // [64][76] scalar rh (swizzled)
    float* sWgh = S2 + 64 * S2_STRIDE;
    float* sBgh = sWgh + 64;
    float* sWxc = sBgh + 64;
    float* sBxc = sWxc + 192;
    float* sWmc = sBxc + 192;
    float* sXb  = sWmc + 192;                  // [2][64]
    float* sMb  = sXb + 128;
    float* sDb  = sMb + 128;

    const int tid = threadIdx.x;
    for (int i = tid; i < 8192; i += 256) sWzr[(i & 63) * 128 + (i >> 6)] = W_hc[i];
    for (int i = tid; i < 4096; i += 256) sWn[(i & 63) * 64 + (i >> 6)] = W_hn[i];
    if (tid < 64) { sWgh[tid] = W_gh[tid]; sBgh[tid] = b_gh[tid]; }
    if (tid < 192) { sWxc[tid] = W_xc[tid]; sBxc[tid] = b_xc[tid]; sWmc[tid] = W_mc[tid]; }

    const int w = tid >> 5, l = tid & 31;
    const int jt = (l & 7) | ((w & 1) << 3);
    const int rt = (l >> 3) | ((w >> 1) << 2);
    const int j0 = jt * 4, r0 = rt * 4;
    const int soff = 4 * (rt & 3);
    const int rowbase = blockIdx.x * 64;
    const float wgx = W_gx[0], bgx0 = b_gx[0];

    float h[4][4];
#pragma unroll
    for (int a = 0; a < 4; a++)
#pragma unroll
        for (int b = 0; b < 4; b++) h[a][b] = 0.f;

    const int myrow = rowbase + (tid & 63);
    float pf_xi = 0.f, pf_xl = 0.f, pf_xm = 0.f, pf_m = 0.f, pf_d = 0.f;
    if (tid < 64) {
        float xi = X_fa[(size_t)myrow * T_], xl = X_last[(size_t)myrow * T_];
        float xm = X_mean[(size_t)myrow * T_], m = X_mask[(size_t)myrow * T_];
        float d = X_delta[(size_t)myrow * T_];
        float gx = __expf(-fmaxf(fmaf(d, wgx, bgx0), 0.f));
        float om = 1.f - m;
        float Xv = m * xi + om * gx * xl + om * (1.f - gx) * xm;
        sXb[tid] = Xv; sMb[tid] = m; sDb[tid] = d;
        o_Xgru[(size_t)myrow * T_] = Xv;
        if (T_ > 1) {
            pf_xi = X_fa   [(size_t)myrow * T_ + 1];
            pf_xl = X_last [(size_t)myrow * T_ + 1];
            pf_xm = X_mean [(size_t)myrow * T_ + 1];
            pf_m  = X_mask [(size_t)myrow * T_ + 1];
            pf_d  = X_delta[(size_t)myrow * T_ + 1];
        }
    }
    __syncthreads();

    for (int t = 0; t < T_; t++) {
        const int cur = t & 1;

        // ---- decay + write scalar h to S1 (one STS.128 per row) ----
#pragma unroll
        for (int rr = 0; rr < 4; rr++) {
            const float d = sDb[cur * 64 + r0 + rr];
#pragma unroll
            for (int jj = 0; jj < 4; jj++) {
                float g = __expf(-fmaxf(fmaf(d, sWgh[j0 + jj], sBgh[j0 + jj]), 0.f));
                h[rr][jj] *= g;
            }
            float4 v; v.x = h[rr][0]; v.y = h[rr][1]; v.z = h[rr][2]; v.w = h[rr][3];
            *(float4*)(S1 + (r0 + rr) * S_STRIDE + soff + j0) = v;
        }
        __syncthreads();   // (B) S1 ready

        // ---- stage t+1 inputs (other parity; overlaps GEMM1) ----
        if (tid < 64 && t + 1 < T_) {
            const float d = pf_d, m = pf_m;
            const float gx = __expf(-fmaxf(fmaf(d, wgx, bgx0), 0.f));
            const float om = 1.f - m;
            const float Xv = m * pf_xi + om * gx * pf_xl + om * (1.f - gx) * pf_xm;
            const int nc = 1 - cur;
            sXb[nc * 64 + tid] = Xv; sMb[nc * 64 + tid] = m; sDb[nc * 64 + tid] = d;
            o_Xgru[(size_t)myrow * T_ + t + 1] = Xv;
            if (t + 2 < T_) {
                pf_xi = X_fa   [(size_t)myrow * T_ + t + 2];
                pf_xl = X_last [(size_t)myrow * T_ + t + 2];
                pf_xm = X_mean [(size_t)myrow * T_ + t + 2];
                pf_m  = X_mask [(size_t)myrow * T_ + t + 2];
                pf_d  = X_delta[(size_t)myrow * T_ + t + 2];
            }
        }

        // ---- GEMM1: z and r; operands LDS.128 per 4 k per row ----
        const float* sbase1 = S1 + r0 * S_STRIDE + soff;
        u64 az[4][2] = {}, ar[4][2] = {};
#pragma unroll 4
        for (int k4 = 0; k4 < 16; k4++) {
            const float* sp = sbase1 + 4 * k4;
            const float4 f0 = *(const float4*)(sp);
            const float4 f1 = *(const float4*)(sp + S_STRIDE);
            const float4 f2v = *(const float4*)(sp + 2 * S_STRIDE);
            const float4 f3 = *(const float4*)(sp + 3 * S_STRIDE);
            const float e0[4] = {f0.x, f0.y, f0.z, f0.w};
            const float e1[4] = {f1.x, f1.y, f1.z, f1.w};
            const float e2[4] = {f2v.x, f2v.y, f2v.z, f2v.w};
            const float e3[4] = {f3.x, f3.y, f3.z, f3.w};
#pragma unroll
            for (int kk = 0; kk < 4; kk++) {
                const int k = 4 * k4 + kk;
                const ulonglong2 wz = *(const ulonglong2*)(sWzr + k * 128 + j0);
                const ulonglong2 wr = *(const ulonglong2*)(sWzr + k * 128 + 64 + j0);
                u64 h0 = f2pk(e0[kk], e0[kk]);
                u64 h1 = f2pk(e1[kk], e1[kk]);
                u64 h2 = f2pk(e2[kk], e2[kk]);
                u64 h3 = f2pk(e3[kk], e3[kk]);
                az[0][0] = ffma2(h0, wz.x, az[0][0]); az[0][1] = ffma2(h0, wz.y, az[0][1]);
                az[1][0] = ffma2(h1, wz.x, az[1][0]); az[1][1] = ffma2(h1, wz.y, az[1][1]);
                az[2][0] = ffma2(h2, wz.x, az[2][0]); az[2][1] = ffma2(h2, wz.y, az[2][1]);
                az[3][0] = ffma2(h3, wz.x, az[3][0]); az[3][1] = ffma2(h3, wz.y, az[3][1]);
                ar[0][0] = ffma2(h0, wr.x, ar[0][0]); ar[0][1] = ffma2(h0, wr.y, ar[0][1]);
                ar[1][0] = ffma2(h1, wr.x, ar[1][0]); ar[1][1] = ffma2(h1, wr.y, ar[1][1]);
                ar[2][0] = ffma2(h2, wr.x, ar[2][0]); ar[2][1] = ffma2(h2, wr.y, ar[2][1]);
                ar[3][0] = ffma2(h3, wr.x, ar[3][0]); ar[3][1] = ffma2(h3, wr.y, ar[3][1]);
            }
        }

        // ---- gates; write scalar rh to S2 ----
        float zreg[4][4];
#pragma unroll
        for (int rr = 0; rr < 4; rr++) {
            const int r = r0 + rr;
            const float Xv = sXb[cur * 64 + r], mv = sMb[cur * 64 + r];
            float a0, a1, a2, a3, c0, c1, c2, c3;
            f2un(az[rr][0], a0, a1); f2un(az[rr][1], a2, a3);
            f2un(ar[rr][0], c0, c1); f2un(ar[rr][1], c2, c3);
            zreg[rr][0] = sigmoida_(a0 + fmaf(Xv, sWxc[j0 + 0], sBxc[j0 + 0]) + mv * sWmc[j0 + 0]);
            zreg[rr][1] = sigmoida_(a1 + fmaf(Xv, sWxc[j0 + 1], sBxc[j0 + 1]) + mv * sWmc[j0 + 1]);
            zreg[rr][2] = sigmoida_(a2 + fmaf(Xv, sWxc[j0 + 2], sBxc[j0 + 2]) + mv * sWmc[j0 + 2]);
            zreg[rr][3] = sigmoida_(a3 + fmaf(Xv, sWxc[j0 + 3], sBxc[j0 + 3]) + mv * sWmc[j0 + 3]);
            float r0g = sigmoida_(c0 + fmaf(Xv, sWxc[64 + j0 + 0], sBxc[64 + j0 + 0]) + mv * sWmc[64 + j0 + 0]);
            float r1g = sigmoida_(c1 + fmaf(Xv, sWxc[64 + j0 + 1], sBxc[64 + j0 + 1]) + mv * sWmc[64 + j0 + 1]);
            float r2g = sigmoida_(c2 + fmaf(Xv, sWxc[64 + j0 + 2], sBxc[64 + j0 + 2]) + mv * sWmc[64 + j0 + 2]);
            float r3g = sigmoida_(c3 + fmaf(Xv, sWxc[64 + j0 + 3], sBxc[64 + j0 + 3]) + mv * sWmc[64 + j0 + 3]);
            float4 rv;
            rv.x = r0g * h[rr][0]; rv.y = r1g * h[rr][1];
            rv.z = r2g * h[rr][2]; rv.w = r3g * h[rr][3];
            *(float4*)(S2 + (r0 + rr) * S2_STRIDE + soff + j0) = rv;
        }
        __syncthreads();   // (D) S2 ready (GEMM1 S1-reads done)

        // ---- GEMM2: candidate; operands LDS.128 per 4 k per row ----
        const float* sbase2 = S2 + r0 * S2_STRIDE + soff;
        u64 an[4][2] = {};
#pragma unroll 4
        for (int k4 = 0; k4 < 16; k4++) {
            const float* sp = sbase2 + 4 * k4;
            const float4 f0 = *(const float4*)(sp);
            const float4 f1 = *(const float4*)(sp + S2_STRIDE);
            const float4 f2v = *(const float4*)(sp + 2 * S2_STRIDE);
            const float4 f3 = *(const float4*)(sp + 3 * S2_STRIDE);
            const float e0[4] = {f0.x, f0.y, f0.z, f0.w};
            const float e1[4] = {f1.x, f1.y, f1.z, f1.w};
            const float e2[4] = {f2v.x, f2v.y, f2v.z, f2v.w};
            const float e3[4] = {f3.x, f3.y, f3.z, f3.w};
#pragma unroll
            for (int kk = 0; kk < 4; kk++) {
                const ulonglong2 wn = *(const ulonglong2*)(sWn + (4 * k4 + kk) * 64 + j0);
                u64 h0 = f2pk(e0[kk], e0[kk]);
                u64 h1 = f2pk(e1[kk], e1[kk]);
                u64 h2 = f2pk(e2[kk], e2[kk]);
                u64 h3 = f2pk(e3[kk], e3[kk]);
                an[0][0] = ffma2(h0, wn.x, an[0][0]); an[0][1] = ffma2(h0, wn.y, an[0][1]);
                an[1][0] = ffma2(h1, wn.x, an[1][0]); an[1][1] = ffma2(h1, wn.y, an[1][1]);
                an[2][0] = ffma2(h2, wn.x, an[2][0]); an[2][1] = ffma2(h2, wn.y, an[2][1]);
                an[3][0] = ffma2(h3, wn.x, an[3][0]); an[3][1] = ffma2(h3, wn.y, an[3][1]);
            }
        }

        // ---- combine + store ----
#pragma unroll
        for (int rr = 0; rr < 4; rr++) {
            const int r = r0 + rr;
            const float Xv = sXb[cur * 64 + r], mv = sMb[cur * 64 + r];
            float n0, n1, n2, n3;
            f2un(an[rr][0], n0, n1); f2un(an[rr][1], n2, n3);
            float p0 = n0 + fmaf(Xv, sWxc[128 + j0 + 0], sBxc[128 + j0 + 0]) + mv * sWmc[128 + j0 + 0];
            float p1 = n1 + fmaf(Xv, sWxc[128 + j0 + 1], sBxc[128 + j0 + 1]) + mv * sWmc[128 + j0 + 1];
            float p2 = n2 + fmaf(Xv, sWxc[128 + j0 + 2], sBxc[128 + j0 + 2]) + mv * sWmc[128 + j0 + 2];
            float p3 = n3 + fmaf(Xv, sWxc[128 + j0 + 3], sBxc[128 + j0 + 3]) + mv * sWmc[128 + j0 + 3];
            float t0 = tanha_(p0), t1 = tanha_(p1), t2 = tanha_(p2), t3 = tanha_(p3);
            h[rr][0] = fmaf(zreg[rr][0], t0 - h[rr][0], h[rr][0]);
            h[rr][1] = fmaf(zreg[rr][1], t1 - h[rr][1], h[rr][1]);
            h[rr][2] = fmaf(zreg[rr][2], t2 - h[rr][2], h[rr][2]);
            h[rr][3] = fmaf(zreg[rr][3], t3 - h[rr][3], h[rr][3]);
            float4 st; st.x = h[rr][0]; st.y = h[rr][1]; st.z = h[rr][2]; st.w = h[rr][3];
            *(float4*)(o_out + (((size_t)(rowbase + r)) * T_ + t) * H_ + j0) = st;
        }
    }
}

// ======================================================================
// Kernel 2: coalesced tile -> shared; logits + softmax + pooling.
// ======================================================================
#define ATT_S 68

__global__ void __launch_bounds__(64) k_attn(
    const float* __restrict__ out,
    const float* __restrict__ W_sT, const float* __restrict__ W_sM)
{
    __shared__ float sT[64 * ATT_S];
    __shared__ float sWt[64], sWm[64], slT[64], slM[64], swT[64], swM[64];
    const int b = blockIdx.x;
    const int tid = threadIdx.x;
    sWt[tid] = W_sT[tid]; sWm[tid] = W_sM[tid];

    const float4* src = (const float4*)(out + (size_t)b * 4096);
#pragma unroll
    for (int i = 0; i < 16; i++) {
        float4 v = src[i * 64 + tid];
        int t = 4 * i + (tid >> 4);
        int hh = (4 * tid) & 63;
        *(float4*)(sT + t * ATT_S + hh) = v;
    }
    __syncthreads();

    float lT = 0.f, lM = 0.f;
    const float* row = sT + tid * ATT_S;
#pragma unroll
    for (int i = 0; i < 16; i++) {
        float4 v = *(const float4*)(row + 4 * i);
        lT += v.x * sWt[4 * i] + v.y * sWt[4 * i + 1] + v.z * sWt[4 * i + 2] + v.w * sWt[4 * i + 3];
        lM += v.x * sWm[4 * i] + v.y * sWm[4 * i + 1] + v.z * sWm[4 * i + 2] + v.w * sWm[4 * i + 3];
    }
    slT[tid] = lT; slM[tid] = lM;
    __syncthreads();

    const int wid = tid >> 5, lane = tid & 31;
    const float* lg = wid ? slM : slT;
    float l0 = lg[lane], l1 = lg[lane + 32];
    float mx = fmaxf(l0, l1);
#pragma unroll
    for (int o = 16; o; o >>= 1) mx = fmaxf(mx, __shfl_xor_sync(0xffffffffu, mx, o));
    float e0 = __expf(l0 - mx), e1 = __expf(l1 - mx);
    float s = e0 + e1;
#pragma unroll
    for (int o = 16; o; o >>= 1) s += __shfl_xor_sync(0xffffffffu, s, o);
    float inv = frcp(s);
    float* sw = wid ? swM : swT;
    sw[lane] = e0 * inv; sw[lane + 32] = e1 * inv;
    __syncthreads();

    float aT = 0.f, aM = 0.f;
#pragma unroll 8
    for (int t = 0; t < 64; t++) {
        float v = sT[t * ATT_S + tid];
        aT = fmaf(swT[t], v, aT);
        aM = fmaf(swM[t], v, aM);
    }
    g_hidT[(size_t)b * 64 + tid] = aT;
    g_hidM[(size_t)b * 64 + tid] = aM;
}

// ======================================================================
// Kernel 3: MLPs — measured-322us R9 version (unchanged).
// ======================================================================
#define MLP_PAD   302
#define W1TILE_F4 800
#define W2TILE_F4 1500
#define WBUF_FL   6000
#define MLP_SMEM  ((128 * MLP_PAD + 2 * WBUF_FL + 128) * 4)

__global__ void __launch_bounds__(256) k_mlp(
    const float* __restrict__ Wt1, const float* __restrict__ bt1,
    const float* __restrict__ Wt2, const float* __restrict__ bt2,
    const float* __restrict__ Wt3, const float* __restrict__ bt3,
    const float* __restrict__ Wm1, const float* __restrict__ bm1,
    const float* __restrict__ Wm2, const float* __restrict__ bm2,
    const float* __restrict__ Wm3, const float* __restrict__ bm3)
{
    extern __shared__ float sact[];
    float* wbuf0 = sact + 128 * MLP_PAD;
    float* wbuf1 = wbuf0 + WBUF_FL;
    float* sraw  = wbuf1 + WBUF_FL;

    const int head = blockIdx.y;
    const float* hid = head ? g_hidM : g_hidT;
    const float* W1 = head ? Wm1 : Wt1;  const float* b1 = head ? bm1 : bt1;
    const float* W2 = head ? Wm2 : Wt2;  const float* b2 = head ? bm2 : bt2;
    const float* W3 = head ? Wm3 : Wt3;  const float* b3 = head ? bm3 : bt3;
    float* rawOut = head ? g_rawM : g_rawT;

    const int tid  = threadIdx.x;
    const int rloc = tid & 127;
    const int half = tid >> 7;
    const int row  = blockIdx.x * 128 + rloc;

    u64 h2[32];
    {
        const ulonglong2* hp = (const ulonglong2*)(hid + (size_t)row * 64);
#pragma unroll
        for (int i = 0; i < 16; i++) { ulonglong2 v = hp[i]; h2[2 * i] = v.x; h2[2 * i + 1] = v.y; }
    }
    float* arow = sact + rloc * MLP_PAD;

    {
        const float4* src = (const float4*)W1;
        float4* dst = (float4*)wbuf0;
        for (int i = tid; i < W1TILE_F4; i += 256) dst[i] = src[i];
    }
    __syncthreads();

    int p = 0;
    for (int s = 0; s < 6; s++) {
        float4 tr[4]; int trn = 0;
        if (s + 1 < 6) {
            const float4* src = (const float4*)(W1 + (s + 1) * 3200);
#pragma unroll
            for (int i = 0; i < 4; i++) {
                int idx = tid + i * 256;
                if (idx < W1TILE_F4) { tr[i] = src[idx]; trn = i + 1; }
            }
        }
        const float* wt = p ? wbuf1 : wbuf0;
        for (int jj = 0; jj < 25; jj++) {
            const int jl = half * 25 + jj;
            const int j  = 50 * s + jl;
            const ulonglong2* wp = (const ulonglong2*)(wt + jl * 64);
            u64 aA = 0, aB = 0;
#pragma unroll
            for (int kk = 0; kk < 16; kk++) {
                ulonglong2 wv = wp[kk];
                aA = ffma2(h2[2 * kk], wv.x, aA);
                aB = ffma2(h2[2 * kk + 1], wv.y, aB);
            }
            arow[j] = eluf_(hadd2(aA) + hadd2(aB) + b1[j]);
        }
        if (s + 1 < 6) {
            float4* dst = (float4*)(p ? wbuf0 : wbuf1);
#pragma unroll
            for (int i = 0; i < 4; i++) {
                int idx = tid + i * 256;
                if (idx < W1TILE_F4 && i < trn) dst[idx] = tr[i];
            }
        }
        __syncthreads();
        p ^= 1;
    }

    {
        const float4* src = (const float4*)W2;
        float4* dst = (float4*)wbuf0;
        for (int i = tid; i < W2TILE_F4; i += 256) dst[i] = src[i];
    }
    __syncthreads();

    float raw = 0.f;
    const u64* ap = (const u64*)arow;
    p = 0;
    for (int s = 0; s < 15; s++) {
        float4 tr[6]; int trn = 0;
        if (s + 1 < 15) {
            const float4* src = (const float4*)(W2 + (size_t)(s + 1) * 6000);
#pragma unroll
            for (int i = 0; i < 6; i++) {
                int idx = tid + i * 256;
                if (idx < W2TILE_F4) { tr[i] = src[idx]; trn = i + 1; }
            }
        }
        const float* wt = p ? wbuf1 : wbuf0;
        u64 aA[10], aB[10];
#pragma unroll
        for (int u = 0; u < 10; u++) { aA[u] = 0; aB[u] = 0; }
        const float* wbase = wt + (half * 10) * 300;
        for (int kk = 0; kk < 75; kk++) {
            u64 a0 = ap[2 * kk], a1 = ap[2 * kk + 1];
#pragma unroll
            for (int u = 0; u < 10; u++) {
                ulonglong2 wv = *(const ulonglong2*)(wbase + u * 300 + 4 * kk);
                aA[u] = ffma2(a0, wv.x, aA[u]);
                aB[u] = ffma2(a1, wv.y, aB[u]);
            }
        }
#pragma unroll
        for (int u = 0; u < 10; u++) {
            const int j = 20 * s + half * 10 + u;
            float sv = hadd2(aA[u]) + hadd2(aB[u]) + b2[j];
            raw = fmaf(eluf_(sv), W3[j], raw);
        }
        if (s + 1 < 15) {
            float4* dst = (float4*)(p ? wbuf0 : wbuf1);
#pragma unroll
            for (int i = 0; i < 6; i++) {
                int idx = tid + i * 256;
                if (idx < W2TILE_F4 && i < trn) dst[idx] = tr[i];
            }
        }
        __syncthreads();
        p ^= 1;
    }

    if (half == 0) sraw[rloc] = raw;
    __syncthreads();
    if (half == 1) rawOut[row] = sraw[rloc] + raw + b3[0];
}

// ======================================================================
// Kernel 4: elementwise, fully coalesced.
// ======================================================================
__global__ void __launch_bounds__(256) k_final(
    const float* __restrict__ fa, const float* __restrict__ TR,
    float* __restrict__ o_Xout, float* __restrict__ o_T10, float* __restrict__ o_M0)
{
    const int gid = blockIdx.x * 256 + threadIdx.x;
    const int b = gid >> 6;
    const int t = gid & 63;
    const float T10 = 0.2f + sigmoidf_(g_rawT[b]) * 4.8f;
    const float M0v = 0.1f + sigmoidf_(g_rawM[b]) * 19.9f;
    if (t == 0) { o_T10[b] = T10; o_M0[b] = M0v; }
    const float e = __expf(-TR[b] / T10);
    const float f = fa[gid];
    const float num = (1.f - e) * __sinf(f);
    const float den = 1.f - __cosf(f) * e;
    o_Xout[gid] = num / den * M0v;
}

// ======================================================================
extern "C" void kernel_launch(void* const* d_in, const int* in_sizes, int n_in,
                              void* d_out, int out_size)
{
    const float* X_fa    = (const float*)d_in[0];
    const float* X_last  = (const float*)d_in[1];
    const float* X_mean  = (const float*)d_in[2];
    const float* X_mask  = (const float*)d_in[3];
    const float* X_delta = (const float*)d_in[4];
    const float* fa_vals = (const float*)d_in[5];
    const float* TR_vals = (const float*)d_in[6];
    const float* W_gx = (const float*)d_in[7];
    const float* b_gx = (const float*)d_in[8];
    const float* W_gh = (const float*)d_in[9];
    const float* b_gh = (const float*)d_in[10];
    const float* W_xc = (const float*)d_in[11];
    const float* b_xc = (const float*)d_in[12];
    const float* W_hn = (const float*)d_in[13];
    const float* W_hc = (const float*)d_in[14];
    const float* W_mc = (const float*)d_in[15];
    const float* W_sT = (const float*)d_in[16];
    const float* W_sM = (const float*)d_in[17];
    const float* Wt1 = (const float*)d_in[18];
    const float* bt1 = (const float*)d_in[19];
    const float* Wt2 = (const float*)d_in[20];
    const float* bt2 = (const float*)d_in[21];
    const float* Wt3 = (const float*)d_in[22];
    const float* bt3 = (const float*)d_in[23];
    const float* Wm1 = (const float*)d_in[24];
    const float* bm1 = (const float*)d_in[25];
    const float* Wm2 = (const float*)d_in[26];
    const float* bm2 = (const float*)d_in[27];
    const float* Wm3 = (const float*)d_in[28];
    const float* bm3 = (const float*)d_in[29];

    float* outp = (float*)d_out;
    float* o_Xout = outp;                       // [B,T]
    float* o_T10  = outp + 1048576;             // [B,1]
    float* o_M0   = outp + 1064960;             // [B,1]
    float* o_out  = outp + 1081344;             // [B,T,H]
    float* o_Xgru = outp + 68190208;            // [B,T]

    cudaFuncSetAttribute(k_gru, cudaFuncAttributeMaxDynamicSharedMemorySize, GRU_SMEM_BYTES);
    cudaFuncSetAttribute(k_mlp, cudaFuncAttributeMaxDynamicSharedMemorySize, MLP_SMEM);

    // shims: ncu capture slot -> k_gru v7b
    k_nop1<<<1, 32>>>();
    k_nop2<<<1, 32>>>();
    k_nop3<<<1, 32>>>();

    k_gru<<<B_ / 64, 256, GRU_SMEM_BYTES>>>(
        X_fa, X_last, X_mean, X_mask, X_delta,
        W_gx, b_gx, W_gh, b_gh, W_xc, b_xc, W_hn, W_hc, W_mc,
        o_out, o_Xgru);

    k_attn<<<B_, 64>>>(o_out, W_sT, W_sM);

    dim3 mgrid(B_ / 128, 2);
    k_mlp<<<mgrid, 256, MLP_SMEM>>>(Wt1, bt1, Wt2, bt2, Wt3, bt3,
                                    Wm1, bm1, Wm2, bm2, Wm3, bm3);

    k_final<<<(B_ * T_) / 256, 256>>>(fa_vals, TR_vals, o_Xout, o_T10, o_M0);
}